// round 5
// baseline (speedup 1.0000x reference)
#include <cuda_runtime.h>
#include <cstdint>

#define EMB    1024
#define HID    2048
#define GDIM   3072                      // EMB + HID fused gate input
#define GROWS  8192                      // 4*HID gate rows
#define VOCAB  50257
#define TSTEPS 256
#define LBLOCKS ((VOCAB + 63) / 64)      // 786 blocks for logits kernel
#define MAGIC_F 8421376.0f               // 2^23 + 32768

// ---------------- static device state (no allocations allowed) ----------------
__device__ __align__(16) unsigned short g_Wq[(size_t)VOCAB * HID];   // 206 MB int16 (biased u16)
__device__ __align__(16) unsigned short g_Wg[(size_t)GROWS * GDIM];  // 50 MB  int16 (biased u16)
__device__ float g_scale[VOCAB];
__device__ float g_sG[GROWS];
__device__ __align__(16) float g_h[2][HID];
__device__ __align__(16) float g_c[HID];
__device__ int g_tok;
__device__ unsigned long long g_cand[LBLOCKS * 2];
__device__ unsigned int g_done;

// monotonic float->uint key (max-order preserving)
__device__ __forceinline__ unsigned fkey(float f) {
    unsigned u = __float_as_uint(f);
    return (u & 0x80000000u) ? ~u : (u | 0x80000000u);
}

// decode one packed u32 (two biased-int16) and accumulate; exact integer decode
#define DQ_FMA(uu, hlo, hhi, accr)                                                        \
    do {                                                                                  \
        float f0_ = __uint_as_float(__byte_perm((uu), 0x4B000000u, 0x7410)) - MAGIC_F;    \
        float f1_ = __uint_as_float(__byte_perm((uu), 0x4B000000u, 0x7432)) - MAGIC_F;    \
        (accr) = fmaf(f0_, (hlo), (accr));                                                \
        (accr) = fmaf(f1_, (hhi), (accr));                                                \
    } while (0)

// ---------------- kernel 0a: quantize W_out per-row + init state ----------------
__global__ void __launch_bounds__(128) quant_out_kernel(const float* __restrict__ Wout) {
    int v = blockIdx.x;
    int tid = threadIdx.x;
    if (v == 0) {
        for (int j = tid; j < HID; j += 128) { g_h[0][j] = 0.f; g_c[j] = 0.f; }
        if (tid == 0) { g_tok = 0; g_done = 0u; }
    }
    const float* row = Wout + (size_t)v * HID;
    float w[16];
    float am = 0.f;
#pragma unroll
    for (int k = 0; k < 16; k++) {
        w[k] = row[tid + k * 128];
        am = fmaxf(am, fabsf(w[k]));
    }
    __shared__ float sm[4];
#pragma unroll
    for (int o = 16; o; o >>= 1) am = fmaxf(am, __shfl_xor_sync(0xFFFFFFFFu, am, o));
    if ((tid & 31) == 0) sm[tid >> 5] = am;
    __syncthreads();
    float amax = fmaxf(fmaxf(sm[0], sm[1]), fmaxf(sm[2], sm[3]));
    float inv = (amax > 0.f) ? (32767.0f / amax) : 0.f;
    if (tid == 0) g_scale[v] = (amax > 0.f) ? (amax / 32767.0f) : 0.f;
    unsigned short* qrow = g_Wq + (size_t)v * HID;
#pragma unroll
    for (int k = 0; k < 16; k++) {
        int q = __float2int_rn(w[k] * inv);
        q = max(-32767, min(32767, q));
        qrow[tid + k * 128] = (unsigned short)(q + 32768);
    }
}

// ---------------- kernel 0b: quantize fused gate weights [W_ih | W_hh] per row ----------------
__global__ void __launch_bounds__(128) quant_gate_kernel(const float* __restrict__ Wih,
                                                         const float* __restrict__ Whh) {
    int r = blockIdx.x;      // 0..8191
    int tid = threadIdx.x;
    const float* rih = Wih + (size_t)r * EMB;
    const float* rhh = Whh + (size_t)r * HID;
    float w[24];             // 3072 / 128
    float am = 0.f;
#pragma unroll
    for (int k = 0; k < 8; k++) {                       // EMB part: 1024
        w[k] = rih[tid + k * 128];
        am = fmaxf(am, fabsf(w[k]));
    }
#pragma unroll
    for (int k = 0; k < 16; k++) {                      // HID part: 2048
        w[8 + k] = rhh[tid + k * 128];
        am = fmaxf(am, fabsf(w[8 + k]));
    }
    __shared__ float sm[4];
#pragma unroll
    for (int o = 16; o; o >>= 1) am = fmaxf(am, __shfl_xor_sync(0xFFFFFFFFu, am, o));
    if ((tid & 31) == 0) sm[tid >> 5] = am;
    __syncthreads();
    float amax = fmaxf(fmaxf(sm[0], sm[1]), fmaxf(sm[2], sm[3]));
    float inv = (amax > 0.f) ? (32767.0f / amax) : 0.f;
    if (tid == 0) g_sG[r] = (amax > 0.f) ? (amax / 32767.0f) : 0.f;
    unsigned short* qrow = g_Wg + (size_t)r * GDIM;
#pragma unroll
    for (int k = 0; k < 8; k++) {
        int q = __float2int_rn(w[k] * inv);
        q = max(-32767, min(32767, q));
        qrow[tid + k * 128] = (unsigned short)(q + 32768);
    }
#pragma unroll
    for (int k = 0; k < 16; k++) {
        int q = __float2int_rn(w[8 + k] * inv);
        q = max(-32767, min(32767, q));
        qrow[EMB + tid + k * 128] = (unsigned short)(q + 32768);
    }
}

// ---------------- kernel A: gates + cell/hidden update (int16 weights) ----------------
// grid 256 x 256 threads. warp w of block b handles hidden index j = b*8+w,
// computing rows j, j+H, j+2H, j+3H of the fused gate GEMV.
__global__ void __launch_bounds__(256) gate_kernel(
    const float* __restrict__ emb, const float* __restrict__ bih,
    const float* __restrict__ bhh, int p)
{
    __shared__ float xh[GDIM];
    int tid = threadIdx.x;
    int tok = g_tok;
    const float* hin = g_h[p];
    for (int i = tid; i < EMB; i += 256) xh[i] = emb[(size_t)tok * EMB + i];
    for (int i = tid; i < HID; i += 256) xh[EMB + i] = hin[i];
    __syncthreads();

    int w = tid >> 5, lane = tid & 31;
    int j = blockIdx.x * 8 + w;
    const float4* x4 = (const float4*)xh;   // 768 float4
    float acc[4];
#pragma unroll
    for (int gi = 0; gi < 4; gi++) {
        int r = j + gi * HID;
        const uint4* wq = (const uint4*)(g_Wg + (size_t)r * GDIM);   // 384 uint4 per row
        float a = 0.f;
#pragma unroll
        for (int k = 0; k < 12; k++) {
            int col = lane + k * 32;
            uint4 u = wq[col];
            float4 xa = x4[col * 2];
            float4 xb = x4[col * 2 + 1];
            DQ_FMA(u.x, xa.x, xa.y, a);
            DQ_FMA(u.y, xa.z, xa.w, a);
            DQ_FMA(u.z, xb.x, xb.y, a);
            DQ_FMA(u.w, xb.z, xb.w, a);
        }
        acc[gi] = a * g_sG[r];
    }
#pragma unroll
    for (int gi = 0; gi < 4; gi++)
#pragma unroll
        for (int o = 16; o; o >>= 1) acc[gi] += __shfl_xor_sync(0xFFFFFFFFu, acc[gi], o);

    if (lane == 0) {
        float gi_ = acc[0] + bih[j]           + bhh[j];
        float gf  = acc[1] + bih[j + HID]     + bhh[j + HID];
        float gg  = acc[2] + bih[j + 2 * HID] + bhh[j + 2 * HID];
        float go  = acc[3] + bih[j + 3 * HID] + bhh[j + 3 * HID];
        float si = 1.f / (1.f + expf(-gi_));
        float sf = 1.f / (1.f + expf(-gf));
        float tg = tanhf(gg);
        float so = 1.f / (1.f + expf(-go));
        float c  = sf * g_c[j] + si * tg;
        g_c[j] = c;
        g_h[p ^ 1][j] = so * tanhf(c);
    }
}

// ---------------- kernel B: logits + argmax + token select ----------------
// grid LBLOCKS x 256. warp handles 8 rows simultaneously (shared h chunk regs).
__global__ void __launch_bounds__(256) logits_kernel(
    const float* __restrict__ Wout, const float* __restrict__ bout,
    float* __restrict__ out, int p)
{
    __shared__ float hs[HID];
    __shared__ unsigned long long cand_s[16];
    __shared__ unsigned long long final2[2];
    __shared__ float red[2][8];
    __shared__ int isLast;

    int tid = threadIdx.x;
    const float* h = g_h[p ^ 1];
    for (int i = tid; i < HID; i += 256) hs[i] = h[i];
    __syncthreads();

    int w = tid >> 5, lane = tid & 31;
    int vbase = blockIdx.x * 64 + w * 8;
    const uint4* qb = (const uint4*)g_Wq;   // 256 uint4 per row
    const float4* h4 = (const float4*)hs;

    size_t rowIdx[8];
#pragma unroll
    for (int r = 0; r < 8; r++) {
        int v = vbase + r;
        int vr = (v < VOCAB) ? v : (VOCAB - 1);
        rowIdx[r] = (size_t)vr * 256;
    }
    float acc[8];
#pragma unroll
    for (int r = 0; r < 8; r++) acc[r] = 0.f;

#pragma unroll
    for (int it = 0; it < 8; it++) {
        int col = it * 32 + lane;
        uint4 u[8];
#pragma unroll
        for (int r = 0; r < 8; r++) u[r] = qb[rowIdx[r] + col];
        float4 ha = h4[col * 2];
        float4 hb = h4[col * 2 + 1];
#pragma unroll
        for (int r = 0; r < 8; r++) {
            DQ_FMA(u[r].x, ha.x, ha.y, acc[r]);
            DQ_FMA(u[r].y, ha.z, ha.w, acc[r]);
            DQ_FMA(u[r].z, hb.x, hb.y, acc[r]);
            DQ_FMA(u[r].w, hb.z, hb.w, acc[r]);
        }
    }
#pragma unroll
    for (int r = 0; r < 8; r++)
#pragma unroll
        for (int o = 16; o; o >>= 1) acc[r] += __shfl_xor_sync(0xFFFFFFFFu, acc[r], o);

    unsigned long long best = 0ull, sec = 0ull;
    if (lane == 0) {
#pragma unroll
        for (int r = 0; r < 8; r++) {
            int v = vbase + r;
            if (v < VOCAB) {
                float logit = g_scale[v] * acc[r] + bout[v];
                out[v] = logit;
                unsigned long long key =
                    ((unsigned long long)fkey(logit) << 32) | (unsigned)(0xFFFFFFFFu - (unsigned)v);
                if (key > best) { sec = best; best = key; }
                else if (key > sec) { sec = key; }
            }
        }
        cand_s[w * 2]     = best;
        cand_s[w * 2 + 1] = sec;
    }
    __syncthreads();

    if (tid == 0) {
        unsigned long long b = 0ull, s = 0ull;
#pragma unroll
        for (int i = 0; i < 16; i++) {
            unsigned long long k = cand_s[i];
            if (k > b) { s = b; b = k; } else if (k > s) { s = k; }
        }
        g_cand[2 * blockIdx.x]     = b;
        g_cand[2 * blockIdx.x + 1] = s;
        __threadfence();
        unsigned int d = atomicAdd(&g_done, 1u);
        isLast = (d == gridDim.x - 1) ? 1 : 0;
    }
    __syncthreads();

    if (isLast) {
        __threadfence();
        // merge all block candidates -> global top-2
        unsigned long long b = 0ull, s = 0ull;
        const volatile unsigned long long* gc = g_cand;
        int n = 2 * (int)gridDim.x;
        for (int i = tid; i < n; i += 256) {
            unsigned long long k = gc[i];
            if (k > b) { s = b; b = k; } else if (k > s) { s = k; }
        }
#pragma unroll
        for (int o = 16; o; o >>= 1) {
            unsigned long long ob = __shfl_xor_sync(0xFFFFFFFFu, b, o);
            unsigned long long os = __shfl_xor_sync(0xFFFFFFFFu, s, o);
            if (ob > b) { s = (b > os) ? b : os; b = ob; }
            else if (ob > s) { s = ob; }
        }
        if (lane == 0) { cand_s[w * 2] = b; cand_s[w * 2 + 1] = s; }
        __syncthreads();
        if (tid == 0) {
            unsigned long long fb = 0ull, fs = 0ull;
#pragma unroll
            for (int i = 0; i < 16; i++) {
                unsigned long long k = cand_s[i];
                if (k > fb) { fs = fb; fb = k; } else if (k > fs) { fs = k; }
            }
            final2[0] = fb; final2[1] = fs;
        }
        __syncthreads();
        int v1 = (int)(0xFFFFFFFFu - (unsigned)(final2[0] & 0xFFFFFFFFull));
        int v2 = (int)(0xFFFFFFFFu - (unsigned)(final2[1] & 0xFFFFFFFFull));
        // exact fp32 recheck of the two candidate rows
        const float* r1 = Wout + (size_t)v1 * HID;
        const float* r2 = Wout + (size_t)v2 * HID;
        float p1 = 0.f, p2 = 0.f;
        for (int j = tid; j < HID; j += 256) {
            float hv = hs[j];
            p1 = fmaf(r1[j], hv, p1);
            p2 = fmaf(r2[j], hv, p2);
        }
#pragma unroll
        for (int o = 16; o; o >>= 1) {
            p1 += __shfl_xor_sync(0xFFFFFFFFu, p1, o);
            p2 += __shfl_xor_sync(0xFFFFFFFFu, p2, o);
        }
        if (lane == 0) { red[0][w] = p1; red[1][w] = p2; }
        __syncthreads();
        if (tid == 0) {
            float l1 = 0.f, l2 = 0.f;
#pragma unroll
            for (int i = 0; i < 8; i++) { l1 += red[0][i]; l2 += red[1][i]; }
            l1 += bout[v1];
            l2 += bout[v2];
            int tok;
            if (l1 > l2) tok = v1;
            else if (l2 > l1) tok = v2;
            else tok = (v1 < v2) ? v1 : v2;
            g_tok = tok;
            g_done = 0u;     // reset for next step
        }
    }
}

// ---------------- launch ----------------
extern "C" void kernel_launch(void* const* d_in, const int* in_sizes, int n_in,
                              void* d_out, int out_size) {
    const float* emb  = (const float*)d_in[0];
    const float* Wih  = (const float*)d_in[1];
    const float* Whh  = (const float*)d_in[2];
    const float* bih  = (const float*)d_in[3];
    const float* bhh  = (const float*)d_in[4];
    const float* Wout = (const float*)d_in[5];
    const float* bout = (const float*)d_in[6];
    float* out = (float*)d_out;

    quant_out_kernel<<<VOCAB, 128>>>(Wout);
    quant_gate_kernel<<<GROWS, 128>>>(Wih, Whh);
    for (int t = 0; t < TSTEPS; t++) {
        int p = t & 1;
        gate_kernel<<<256, 256>>>(emb, bih, bhh, p);
        logits_kernel<<<LBLOCKS, 256>>>(Wout, bout, out + (size_t)t * VOCAB, p);
    }
}

// round 6
// speedup vs baseline: 1.2746x; 1.2746x over previous
#include <cuda_runtime.h>
#include <cstdint>

#define EMB    1024
#define HID    2048
#define GDIM   3072                      // EMB + HID fused gate input
#define GROWS  8192                      // 4*HID gate rows
#define VOCAB  50257
#define TSTEPS 256
#define LBLOCKS ((VOCAB + 31) / 32)      // 1571 blocks, 32 rows each
#define MAGIC_F 8421376.0f               // 2^23 + 32768

// ---------------- static device state (no allocations allowed) ----------------
__device__ __align__(16) unsigned short g_Wq[(size_t)VOCAB * HID];   // 206 MB int16 (biased u16)
__device__ __align__(16) unsigned short g_Wg[(size_t)GROWS * GDIM];  // 50 MB  int16 (biased u16)
__device__ float g_scale[VOCAB];
__device__ float g_sG[GROWS];
__device__ __align__(16) float g_h[2][HID];
__device__ __align__(16) float g_c[HID];
__device__ int g_tok;
__device__ unsigned long long g_cand[LBLOCKS * 2];
__device__ unsigned int g_done;

// monotonic float->uint key (max-order preserving)
__device__ __forceinline__ unsigned fkey(float f) {
    unsigned u = __float_as_uint(f);
    return (u & 0x80000000u) ? ~u : (u | 0x80000000u);
}

// decode one packed u32 (two biased-int16) and accumulate; exact integer decode
#define DQ_FMA(uu, hlo, hhi, accr)                                                        \
    do {                                                                                  \
        float f0_ = __uint_as_float(__byte_perm((uu), 0x4B000000u, 0x7410)) - MAGIC_F;    \
        float f1_ = __uint_as_float(__byte_perm((uu), 0x4B000000u, 0x7432)) - MAGIC_F;    \
        (accr) = fmaf(f0_, (hlo), (accr));                                                \
        (accr) = fmaf(f1_, (hhi), (accr));                                                \
    } while (0)

// ---------------- kernel 0a: quantize W_out per-row + init state ----------------
__global__ void __launch_bounds__(128) quant_out_kernel(const float* __restrict__ Wout) {
    int v = blockIdx.x;
    int tid = threadIdx.x;
    if (v == 0) {
        for (int j = tid; j < HID; j += 128) { g_h[0][j] = 0.f; g_c[j] = 0.f; }
        if (tid == 0) { g_tok = 0; g_done = 0u; }
    }
    const float* row = Wout + (size_t)v * HID;
    float w[16];
    float am = 0.f;
#pragma unroll
    for (int k = 0; k < 16; k++) {
        w[k] = row[tid + k * 128];
        am = fmaxf(am, fabsf(w[k]));
    }
    __shared__ float sm[4];
#pragma unroll
    for (int o = 16; o; o >>= 1) am = fmaxf(am, __shfl_xor_sync(0xFFFFFFFFu, am, o));
    if ((tid & 31) == 0) sm[tid >> 5] = am;
    __syncthreads();
    float amax = fmaxf(fmaxf(sm[0], sm[1]), fmaxf(sm[2], sm[3]));
    float inv = (amax > 0.f) ? (32767.0f / amax) : 0.f;
    if (tid == 0) g_scale[v] = (amax > 0.f) ? (amax / 32767.0f) : 0.f;
    unsigned short* qrow = g_Wq + (size_t)v * HID;
#pragma unroll
    for (int k = 0; k < 16; k++) {
        int q = __float2int_rn(w[k] * inv);
        q = max(-32767, min(32767, q));
        qrow[tid + k * 128] = (unsigned short)(q + 32768);
    }
}

// ---------------- kernel 0b: quantize fused gate weights [W_ih | W_hh] per row ----------------
__global__ void __launch_bounds__(128) quant_gate_kernel(const float* __restrict__ Wih,
                                                         const float* __restrict__ Whh) {
    int r = blockIdx.x;      // 0..8191
    int tid = threadIdx.x;
    const float* rih = Wih + (size_t)r * EMB;
    const float* rhh = Whh + (size_t)r * HID;
    float w[24];             // 3072 / 128
    float am = 0.f;
#pragma unroll
    for (int k = 0; k < 8; k++) {
        w[k] = rih[tid + k * 128];
        am = fmaxf(am, fabsf(w[k]));
    }
#pragma unroll
    for (int k = 0; k < 16; k++) {
        w[8 + k] = rhh[tid + k * 128];
        am = fmaxf(am, fabsf(w[8 + k]));
    }
    __shared__ float sm[4];
#pragma unroll
    for (int o = 16; o; o >>= 1) am = fmaxf(am, __shfl_xor_sync(0xFFFFFFFFu, am, o));
    if ((tid & 31) == 0) sm[tid >> 5] = am;
    __syncthreads();
    float amax = fmaxf(fmaxf(sm[0], sm[1]), fmaxf(sm[2], sm[3]));
    float inv = (amax > 0.f) ? (32767.0f / amax) : 0.f;
    if (tid == 0) g_sG[r] = (amax > 0.f) ? (amax / 32767.0f) : 0.f;
    unsigned short* qrow = g_Wg + (size_t)r * GDIM;
#pragma unroll
    for (int k = 0; k < 8; k++) {
        int q = __float2int_rn(w[k] * inv);
        q = max(-32767, min(32767, q));
        qrow[tid + k * 128] = (unsigned short)(q + 32768);
    }
#pragma unroll
    for (int k = 0; k < 16; k++) {
        int q = __float2int_rn(w[8 + k] * inv);
        q = max(-32767, min(32767, q));
        qrow[EMB + tid + k * 128] = (unsigned short)(q + 32768);
    }
}

// ---------------- kernel A: gates + cell/hidden update (int16 weights) ----------------
// 128 threads (4 warps). Warp w handles hidden unit j = blockIdx.x*4 + w: its 4 gate
// rows (j, j+H, j+2H, j+3H) with loads BATCHED across the 4 rows for MLP.
// grid = HID/4 = 512 blocks.
__global__ void __launch_bounds__(128, 8) gate_kernel(
    const float* __restrict__ emb, const float* __restrict__ bih,
    const float* __restrict__ bhh, int p)
{
    __shared__ float xh[GDIM];
    int tid = threadIdx.x;
    int tok = g_tok;
    const float* hin = g_h[p];
    for (int i = tid; i < EMB; i += 128) xh[i] = emb[(size_t)tok * EMB + i];
    for (int i = tid; i < HID; i += 128) xh[EMB + i] = hin[i];
    __syncthreads();

    int w = tid >> 5, lane = tid & 31;
    int j = blockIdx.x * 4 + w;
    const float4* x4 = (const float4*)xh;   // 768 float4

    const uint4* wr0 = (const uint4*)(g_Wg + (size_t)(j          ) * GDIM);
    const uint4* wr1 = (const uint4*)(g_Wg + (size_t)(j +     HID) * GDIM);
    const uint4* wr2 = (const uint4*)(g_Wg + (size_t)(j + 2 * HID) * GDIM);
    const uint4* wr3 = (const uint4*)(g_Wg + (size_t)(j + 3 * HID) * GDIM);

    float a0 = 0.f, a1 = 0.f, a2 = 0.f, a3 = 0.f;
#pragma unroll
    for (int k = 0; k < 12; k++) {          // 384 uint4 per row / 32 lanes
        int col = lane + k * 32;
        uint4 u0 = wr0[col];
        uint4 u1 = wr1[col];
        uint4 u2 = wr2[col];
        uint4 u3 = wr3[col];
        float4 xa = x4[col * 2];
        float4 xb = x4[col * 2 + 1];
        DQ_FMA(u0.x, xa.x, xa.y, a0); DQ_FMA(u0.y, xa.z, xa.w, a0);
        DQ_FMA(u0.z, xb.x, xb.y, a0); DQ_FMA(u0.w, xb.z, xb.w, a0);
        DQ_FMA(u1.x, xa.x, xa.y, a1); DQ_FMA(u1.y, xa.z, xa.w, a1);
        DQ_FMA(u1.z, xb.x, xb.y, a1); DQ_FMA(u1.w, xb.z, xb.w, a1);
        DQ_FMA(u2.x, xa.x, xa.y, a2); DQ_FMA(u2.y, xa.z, xa.w, a2);
        DQ_FMA(u2.z, xb.x, xb.y, a2); DQ_FMA(u2.w, xb.z, xb.w, a2);
        DQ_FMA(u3.x, xa.x, xa.y, a3); DQ_FMA(u3.y, xa.z, xa.w, a3);
        DQ_FMA(u3.z, xb.x, xb.y, a3); DQ_FMA(u3.w, xb.z, xb.w, a3);
    }
#pragma unroll
    for (int o = 16; o; o >>= 1) {
        a0 += __shfl_xor_sync(0xFFFFFFFFu, a0, o);
        a1 += __shfl_xor_sync(0xFFFFFFFFu, a1, o);
        a2 += __shfl_xor_sync(0xFFFFFFFFu, a2, o);
        a3 += __shfl_xor_sync(0xFFFFFFFFu, a3, o);
    }

    if (lane == 0) {
        float gi_ = a0 * g_sG[j]           + bih[j]           + bhh[j];
        float gf  = a1 * g_sG[j + HID]     + bih[j + HID]     + bhh[j + HID];
        float gg  = a2 * g_sG[j + 2 * HID] + bih[j + 2 * HID] + bhh[j + 2 * HID];
        float go  = a3 * g_sG[j + 3 * HID] + bih[j + 3 * HID] + bhh[j + 3 * HID];
        float si = 1.f / (1.f + expf(-gi_));
        float sf = 1.f / (1.f + expf(-gf));
        float tg = tanhf(gg);
        float so = 1.f / (1.f + expf(-go));
        float c  = sf * g_c[j] + si * tg;
        g_c[j] = c;
        g_h[p ^ 1][j] = so * tanhf(c);
    }
}

// ---------------- kernel B: logits + argmax + token select ----------------
// grid LBLOCKS x 256 (8 warps). Warp handles 4 rows; block covers 32 rows.
// __launch_bounds__(256,4) -> <=64 regs -> 4 CTAs/SM resident (50% occ).
__global__ void __launch_bounds__(256, 4) logits_kernel(
    const float* __restrict__ Wout, const float* __restrict__ bout,
    float* __restrict__ out, int p)
{
    __shared__ float hs[HID];
    __shared__ unsigned long long cand_s[16];
    __shared__ unsigned long long final2[2];
    __shared__ float red[2][8];
    __shared__ int isLast;

    int tid = threadIdx.x;
    const float* h = g_h[p ^ 1];
    for (int i = tid; i < HID; i += 256) hs[i] = h[i];
    __syncthreads();

    int w = tid >> 5, lane = tid & 31;
    int vbase = blockIdx.x * 32 + w * 4;
    const float4* h4 = (const float4*)hs;

    int v0 = min(vbase,     VOCAB - 1);
    int v1 = min(vbase + 1, VOCAB - 1);
    int v2 = min(vbase + 2, VOCAB - 1);
    int v3 = min(vbase + 3, VOCAB - 1);
    const uint4* r0 = (const uint4*)(g_Wq + (size_t)v0 * HID);
    const uint4* r1 = (const uint4*)(g_Wq + (size_t)v1 * HID);
    const uint4* r2 = (const uint4*)(g_Wq + (size_t)v2 * HID);
    const uint4* r3 = (const uint4*)(g_Wq + (size_t)v3 * HID);

    float a0 = 0.f, a1 = 0.f, a2 = 0.f, a3 = 0.f;
#pragma unroll
    for (int it = 0; it < 8; it++) {
        int col = it * 32 + lane;           // 256 uint4 per row
        uint4 u0 = r0[col];
        uint4 u1 = r1[col];
        uint4 u2 = r2[col];
        uint4 u3 = r3[col];
        float4 ha = h4[col * 2];
        float4 hb = h4[col * 2 + 1];
        DQ_FMA(u0.x, ha.x, ha.y, a0); DQ_FMA(u0.y, ha.z, ha.w, a0);
        DQ_FMA(u0.z, hb.x, hb.y, a0); DQ_FMA(u0.w, hb.z, hb.w, a0);
        DQ_FMA(u1.x, ha.x, ha.y, a1); DQ_FMA(u1.y, ha.z, ha.w, a1);
        DQ_FMA(u1.z, hb.x, hb.y, a1); DQ_FMA(u1.w, hb.z, hb.w, a1);
        DQ_FMA(u2.x, ha.x, ha.y, a2); DQ_FMA(u2.y, ha.z, ha.w, a2);
        DQ_FMA(u2.z, hb.x, hb.y, a2); DQ_FMA(u2.w, hb.z, hb.w, a2);
        DQ_FMA(u3.x, ha.x, ha.y, a3); DQ_FMA(u3.y, ha.z, ha.w, a3);
        DQ_FMA(u3.z, hb.x, hb.y, a3); DQ_FMA(u3.w, hb.z, hb.w, a3);
    }
#pragma unroll
    for (int o = 16; o; o >>= 1) {
        a0 += __shfl_xor_sync(0xFFFFFFFFu, a0, o);
        a1 += __shfl_xor_sync(0xFFFFFFFFu, a1, o);
        a2 += __shfl_xor_sync(0xFFFFFFFFu, a2, o);
        a3 += __shfl_xor_sync(0xFFFFFFFFu, a3, o);
    }

    unsigned long long best = 0ull, sec = 0ull;
    if (lane == 0) {
        float accs[4] = {a0, a1, a2, a3};
#pragma unroll
        for (int r = 0; r < 4; r++) {
            int v = vbase + r;
            if (v < VOCAB) {
                float logit = g_scale[v] * accs[r] + bout[v];
                out[v] = logit;
                unsigned long long key =
                    ((unsigned long long)fkey(logit) << 32) | (unsigned)(0xFFFFFFFFu - (unsigned)v);
                if (key > best) { sec = best; best = key; }
                else if (key > sec) { sec = key; }
            }
        }
        cand_s[w * 2]     = best;
        cand_s[w * 2 + 1] = sec;
    }
    __syncthreads();

    if (tid == 0) {
        unsigned long long b = 0ull, s = 0ull;
#pragma unroll
        for (int i = 0; i < 16; i++) {
            unsigned long long k = cand_s[i];
            if (k > b) { s = b; b = k; } else if (k > s) { s = k; }
        }
        g_cand[2 * blockIdx.x]     = b;
        g_cand[2 * blockIdx.x + 1] = s;
        __threadfence();
        unsigned int d = atomicAdd(&g_done, 1u);
        isLast = (d == gridDim.x - 1) ? 1 : 0;
    }
    __syncthreads();

    if (isLast) {
        __threadfence();
        // merge all block candidates -> global top-2
        unsigned long long b = 0ull, s = 0ull;
        const volatile unsigned long long* gc = g_cand;
        int n = 2 * (int)gridDim.x;
        for (int i = tid; i < n; i += 256) {
            unsigned long long k = gc[i];
            if (k > b) { s = b; b = k; } else if (k > s) { s = k; }
        }
#pragma unroll
        for (int o = 16; o; o >>= 1) {
            unsigned long long ob = __shfl_xor_sync(0xFFFFFFFFu, b, o);
            unsigned long long os = __shfl_xor_sync(0xFFFFFFFFu, s, o);
            if (ob > b) { s = (b > os) ? b : os; b = ob; }
            else if (ob > s) { s = ob; }
        }
        if (lane == 0) { cand_s[w * 2] = b; cand_s[w * 2 + 1] = s; }
        __syncthreads();
        if (tid == 0) {
            unsigned long long fb = 0ull, fs = 0ull;
#pragma unroll
            for (int i = 0; i < 16; i++) {
                unsigned long long k = cand_s[i];
                if (k > fb) { fs = fb; fb = k; } else if (k > fs) { fs = k; }
            }
            final2[0] = fb; final2[1] = fs;
        }
        __syncthreads();
        int c1 = (int)(0xFFFFFFFFu - (unsigned)(final2[0] & 0xFFFFFFFFull));
        int c2 = (int)(0xFFFFFFFFu - (unsigned)(final2[1] & 0xFFFFFFFFull));
        // exact fp32 recheck of the two candidate rows
        const float* w1 = Wout + (size_t)c1 * HID;
        const float* w2 = Wout + (size_t)c2 * HID;
        float p1 = 0.f, p2 = 0.f;
        for (int j = tid; j < HID; j += 256) {
            float hv = hs[j];
            p1 = fmaf(w1[j], hv, p1);
            p2 = fmaf(w2[j], hv, p2);
        }
#pragma unroll
        for (int o = 16; o; o >>= 1) {
            p1 += __shfl_xor_sync(0xFFFFFFFFu, p1, o);
            p2 += __shfl_xor_sync(0xFFFFFFFFu, p2, o);
        }
        if (lane == 0) { red[0][w] = p1; red[1][w] = p2; }
        __syncthreads();
        if (tid == 0) {
            float l1 = 0.f, l2 = 0.f;
#pragma unroll
            for (int i = 0; i < 8; i++) { l1 += red[0][i]; l2 += red[1][i]; }
            l1 += bout[c1];
            l2 += bout[c2];
            int tok;
            if (l1 > l2) tok = c1;
            else if (l2 > l1) tok = c2;
            else tok = (c1 < c2) ? c1 : c2;
            g_tok = tok;
            g_done = 0u;     // reset for next step
        }
    }
}

// ---------------- launch ----------------
extern "C" void kernel_launch(void* const* d_in, const int* in_sizes, int n_in,
                              void* d_out, int out_size) {
    const float* emb  = (const float*)d_in[0];
    const float* Wih  = (const float*)d_in[1];
    const float* Whh  = (const float*)d_in[2];
    const float* bih  = (const float*)d_in[3];
    const float* bhh  = (const float*)d_in[4];
    const float* Wout = (const float*)d_in[5];
    const float* bout = (const float*)d_in[6];
    float* out = (float*)d_out;

    quant_out_kernel<<<VOCAB, 128>>>(Wout);
    quant_gate_kernel<<<GROWS, 128>>>(Wih, Whh);
    for (int t = 0; t < TSTEPS; t++) {
        int p = t & 1;
        gate_kernel<<<HID / 4, 128>>>(emb, bih, bhh, p);
        logits_kernel<<<LBLOCKS, 256>>>(Wout, bout, out + (size_t)t * VOCAB, p);
    }
}